// round 6
// baseline (speedup 1.0000x reference)
#include <cuda_runtime.h>
#include <cuda_bf16.h>

#define T_DIM 512
#define B_DIM 512
#define FDIM  64
#define H_DIM 128
#define G3    384   // 3*H
#define BSTRIDE ((size_t)T_DIM * G3)
#define NTH   768                      // scan threads per block
#define WSM_BYTES (16 * NTH * 2 * 4)   // 96 KB: per-thread k-half upper 32 weights

// ---- scratch (device globals; no allocation) ----
__device__ float g_xw[(size_t)B_DIM * T_DIM * G3];   // x@Wx + b_in per (b,t)

// packed f32x2 fused multiply-add: d = a*b + d (per 32-bit lane)
__device__ __forceinline__ void ffma2(unsigned long long& d,
                                      unsigned long long a,
                                      unsigned long long b) {
    asm("fma.rn.f32x2 %0, %1, %2, %3;" : "=l"(d) : "l"(a), "l"(b), "l"(d));
}
__device__ __forceinline__ unsigned long long packf2(float lo, float hi) {
    unsigned long long u;
    asm("mov.b64 %0, {%1,%2};" : "=l"(u) : "f"(lo), "f"(hi));
    return u;
}
__device__ __forceinline__ float ull_hsum(unsigned long long u) {
    float lo, hi;
    asm("mov.b64 {%0,%1}, %2;" : "=f"(lo), "=f"(hi) : "l"(u));
    return lo + hi;
}
__device__ __forceinline__ float fsigmoid(float x) {
    return __fdividef(1.f, 1.f + __expf(-x));
}
__device__ __forceinline__ float ftanh(float x) {
    float e = __expf(2.f * x);
    return 1.f - __fdividef(2.f, e + 1.f);
}

// ---------------------------------------------------------------------------
// Kernel 1: xw[row,:] = x[row,:] @ Wx + b_in.  (unchanged from round 5)
// 64 rows/block, 384 threads, weights re-read per k4 as coalesced L1-hit
// LDG.32; low regs -> 2 CTAs/SM (24 warps).
// ---------------------------------------------------------------------------
__global__ void __launch_bounds__(384, 2) xw_kernel(const float* __restrict__ inputs,
                                                    const float* __restrict__ Wx,
                                                    const float* __restrict__ bias) {
    __shared__ __align__(16) float xs[64][FDIM];   // 16 KB
    const int row0 = blockIdx.x * 64;
    const int j    = threadIdx.x;

    for (int i = j; i < 64 * FDIM; i += 384) {
        int r = i >> 6, k = i & 63;
        xs[r][k] = inputs[(size_t)(row0 + r) * 65 + k];
    }
    const float bi = bias[j];
    __syncthreads();

    #pragma unroll 1
    for (int rt = 0; rt < 8; rt++) {
        unsigned long long acc[8];
        #pragma unroll
        for (int r = 0; r < 8; r++) acc[r] = 0ull;

        #pragma unroll
        for (int k4 = 0; k4 < FDIM / 4; k4++) {
            float w0 = __ldg(&Wx[(k4 * 4 + 0) * G3 + j]);
            float w1 = __ldg(&Wx[(k4 * 4 + 1) * G3 + j]);
            float w2 = __ldg(&Wx[(k4 * 4 + 2) * G3 + j]);
            float w3 = __ldg(&Wx[(k4 * 4 + 3) * G3 + j]);
            unsigned long long wA = packf2(w0, w1);
            unsigned long long wB = packf2(w2, w3);
            #pragma unroll
            for (int r = 0; r < 8; r++) {
                ulonglong2 x = *reinterpret_cast<const ulonglong2*>(
                    &xs[rt * 8 + r][k4 * 4]);
                ffma2(acc[r], wA, x.x);
                ffma2(acc[r], wB, x.y);
            }
        }
        #pragma unroll
        for (int r = 0; r < 8; r++)
            g_xw[(size_t)(row0 + rt * 8 + r) * G3 + j] = ull_hsum(acc[r]) + bi;
    }
}

// ---------------------------------------------------------------------------
// Kernel 2: GRU scan + fused head. 128 blocks x 768 threads, 4 batches/block.
// SPLIT-K: lane pair (2L, 2L+1) shares column col=t>>1; parity kh=t&1 picks
// the k-half [64*kh, 64*kh+64). Per thread: 32 weights in regs (16 packed) +
// 32 in smem. Partials combined with shfl.xor(1). 6 warps/SMSP (2x round 5)
// to hide LDS/FMA latency; ~75 regs/thread fits the 85-reg budget.
// ---------------------------------------------------------------------------
extern __shared__ float wsm[];   // [16][NTH][2]: pair (kbase+32+2*i2, +1) at [i2][t]

__global__ void __launch_bounds__(NTH, 1) gru_scan_kernel(
        const float* __restrict__ inputs,
        const float* __restrict__ Wh,
        const float* __restrict__ bias,
        const float* __restrict__ W_state,
        const float* __restrict__ w1,
        const float* __restrict__ b1,
        const float* __restrict__ gamma,
        const float* __restrict__ beta,
        const float* __restrict__ mean,
        const float* __restrict__ var,
        const float* __restrict__ w2,
        const float* __restrict__ b2,
        float* __restrict__ out) {
    __shared__ __align__(16) float hs[4][H_DIM];    // h, batch-major
    __shared__ float ge[4][G3];                     // recurrent preact + b_rec
    __shared__ float xvs[4][G3];                    // input preact (x@Wx + b_in)
    __shared__ float red[4][64];                    // head partial products

    const int t     = threadIdx.x;
    const int col   = t >> 1;
    const int kh    = t & 1;
    const int kbase = kh * 64;
    const int b0    = blockIdx.x * 4;

    // weights k = kbase .. kbase+31 -> packed registers
    unsigned long long wk[16];
    #pragma unroll
    for (int kk = 0; kk < 16; kk++) {
        float lo = __ldg(&Wh[(kbase + 2 * kk) * G3 + col]);
        float hi = __ldg(&Wh[(kbase + 2 * kk + 1) * G3 + col]);
        wk[kk] = packf2(lo, hi);
    }
    // weights k = kbase+32 .. kbase+63 -> smem [i2][t] (8B/lane, conflict-free)
    #pragma unroll 4
    for (int i2 = 0; i2 < 16; i2++) {
        wsm[((size_t)i2 * NTH + t) * 2 + 0] = __ldg(&Wh[(kbase + 32 + 2 * i2) * G3 + col]);
        wsm[((size_t)i2 * NTH + t) * 2 + 1] = __ldg(&Wh[(kbase + 32 + 2 * i2 + 1) * G3 + col]);
    }

    if (t < 4 * H_DIM) (&hs[0][0])[t] = 0.f;
    const float brec = bias[G3 + col];
    const float* __restrict__ xwp = g_xw + (size_t)b0 * BSTRIDE + col;
    __syncthreads();

    for (int step = 0; step < T_DIM; step++) {
        const size_t so = (size_t)step * G3;
        // both lanes of a pair load the same address (warp broadcast, no extra lines)
        float xv0 = xwp[0 * BSTRIDE + so];
        float xv1 = xwp[1 * BSTRIDE + so];
        float xv2 = xwp[2 * BSTRIDE + so];
        float xv3 = xwp[3 * BSTRIDE + so];

        unsigned long long a0 = 0ull, a1 = 0ull, a2 = 0ull, a3 = 0ull;

        // k-half lower 32: weights from registers
        #pragma unroll
        for (int k4 = 0; k4 < 8; k4++) {
            const int k = kbase + 4 * k4;
            ulonglong2 h0 = *reinterpret_cast<const ulonglong2*>(&hs[0][k]);
            ffma2(a0, wk[2 * k4], h0.x);
            ffma2(a0, wk[2 * k4 + 1], h0.y);
            ulonglong2 h1 = *reinterpret_cast<const ulonglong2*>(&hs[1][k]);
            ffma2(a1, wk[2 * k4], h1.x);
            ffma2(a1, wk[2 * k4 + 1], h1.y);
            ulonglong2 h2 = *reinterpret_cast<const ulonglong2*>(&hs[2][k]);
            ffma2(a2, wk[2 * k4], h2.x);
            ffma2(a2, wk[2 * k4 + 1], h2.y);
            ulonglong2 h3 = *reinterpret_cast<const ulonglong2*>(&hs[3][k]);
            ffma2(a3, wk[2 * k4], h3.x);
            ffma2(a3, wk[2 * k4 + 1], h3.y);
        }
        // k-half upper 32: weights from smem
        #pragma unroll
        for (int k4 = 0; k4 < 8; k4++) {
            const int k = kbase + 32 + 4 * k4;
            unsigned long long wA = *reinterpret_cast<const unsigned long long*>(
                &wsm[((size_t)(2 * k4) * NTH + t) * 2]);
            unsigned long long wB = *reinterpret_cast<const unsigned long long*>(
                &wsm[((size_t)(2 * k4 + 1) * NTH + t) * 2]);
            ulonglong2 h0 = *reinterpret_cast<const ulonglong2*>(&hs[0][k]);
            ffma2(a0, wA, h0.x);
            ffma2(a0, wB, h0.y);
            ulonglong2 h1 = *reinterpret_cast<const ulonglong2*>(&hs[1][k]);
            ffma2(a1, wA, h1.x);
            ffma2(a1, wB, h1.y);
            ulonglong2 h2 = *reinterpret_cast<const ulonglong2*>(&hs[2][k]);
            ffma2(a2, wA, h2.x);
            ffma2(a2, wB, h2.y);
            ulonglong2 h3 = *reinterpret_cast<const ulonglong2*>(&hs[3][k]);
            ffma2(a3, wA, h3.x);
            ffma2(a3, wB, h3.y);
        }

        // combine k-halves across the lane pair
        float s0 = ull_hsum(a0); s0 += __shfl_xor_sync(0xFFFFFFFFu, s0, 1);
        float s1 = ull_hsum(a1); s1 += __shfl_xor_sync(0xFFFFFFFFu, s1, 1);
        float s2 = ull_hsum(a2); s2 += __shfl_xor_sync(0xFFFFFFFFu, s2, 1);
        float s3 = ull_hsum(a3); s3 += __shfl_xor_sync(0xFFFFFFFFu, s3, 1);

        if (kh == 0) {
            ge[0][col] = s0 + brec;  xvs[0][col] = xv0;
            ge[1][col] = s1 + brec;  xvs[1][col] = xv1;
            ge[2][col] = s2 + brec;  xvs[2][col] = xv2;
            ge[3][col] = s3 + brec;  xvs[3][col] = xv3;
        }
        __syncthreads();

        // activations: 512 items, exactly one per thread for t < 512
        if (t < 4 * H_DIM) {
            int b = t >> 7, j = t & 127;
            float z  = fsigmoid(ge[b][j]       + xvs[b][j]);
            float r  = fsigmoid(ge[b][128 + j] + xvs[b][128 + j]);
            float hh = ftanh(xvs[b][256 + j] + r * ge[b][256 + j]);
            hs[b][j] = z * hs[b][j] + (1.f - z) * hh;
        }
        __syncthreads();
    }

    // ---- fused head: hidden += W_state[idx]; out = BN(relu(hid@w1+b1)) @ w2 + b2
    if (t < 4 * H_DIM) {
        int bb = t >> 7, j = t & 127;
        float st = inputs[((size_t)(b0 + bb) * T_DIM + (T_DIM - 1)) * 65 + 64];
        int idx = (int)st;
        idx = idx < 0 ? 0 : (idx > 2 ? 2 : idx);
        xvs[bb][j] = hs[bb][j] + W_state[idx * H_DIM + j];
    }
    __syncthreads();

    if (t < 256) {
        int bb = t >> 6, tt = t & 63;
        float a = b1[tt];
        #pragma unroll 8
        for (int k = 0; k < H_DIM; k++)
            a = fmaf(xvs[bb][k], w1[k * 64 + tt], a);
        a = fmaxf(a, 0.f);
        a = (a - mean[tt]) * rsqrtf(var[tt] + 1e-3f) * gamma[tt] + beta[tt];
        red[bb][tt] = a * w2[tt];
    }
    __syncthreads();

    if (t < 4) {
        float s = b2[0];
        #pragma unroll 8
        for (int k = 0; k < 64; k++) s += red[t][k];
        out[b0 + t] = s;
    }
}

// ---------------------------------------------------------------------------
extern "C" void kernel_launch(void* const* d_in, const int* in_sizes, int n_in,
                              void* d_out, int out_size) {
    const float* inputs  = (const float*)d_in[0];
    const float* Wx      = (const float*)d_in[1];
    const float* Wh      = (const float*)d_in[2];
    const float* bias    = (const float*)d_in[3];
    const float* W_state = (const float*)d_in[4];
    const float* w1      = (const float*)d_in[5];
    const float* b1      = (const float*)d_in[6];
    const float* gamma   = (const float*)d_in[7];
    const float* beta    = (const float*)d_in[8];
    const float* mean    = (const float*)d_in[9];
    const float* var     = (const float*)d_in[10];
    const float* w2      = (const float*)d_in[11];
    const float* b2      = (const float*)d_in[12];
    float* out = (float*)d_out;

    cudaFuncSetAttribute(gru_scan_kernel,
                         cudaFuncAttributeMaxDynamicSharedMemorySize, WSM_BYTES);

    xw_kernel<<<(B_DIM * T_DIM) / 64, 384>>>(inputs, Wx, bias);
    gru_scan_kernel<<<B_DIM / 4, NTH, WSM_BYTES>>>(
        inputs, Wh, bias, W_state, w1, b1,
        gamma, beta, mean, var, w2, b2, out);
}

// round 8
// speedup vs baseline: 1.8730x; 1.8730x over previous
#include <cuda_runtime.h>
#include <cuda_bf16.h>

#define T_DIM 512
#define B_DIM 512
#define FDIM  64
#define H_DIM 128
#define G3    384   // 3*H
#define BSTRIDE ((size_t)T_DIM * G3)

// ---- scratch (device globals; no allocation) ----
__device__ float g_xw[(size_t)B_DIM * T_DIM * G3];   // x@Wx + b_in per (b,t)

// packed f32x2 fused multiply-add: d = a*b + d (per 32-bit lane)
__device__ __forceinline__ void ffma2(unsigned long long& d,
                                      unsigned long long a,
                                      unsigned long long b) {
    asm("fma.rn.f32x2 %0, %1, %2, %3;" : "=l"(d) : "l"(a), "l"(b), "l"(d));
}
__device__ __forceinline__ unsigned long long packf2(float lo, float hi) {
    unsigned long long u;
    asm("mov.b64 %0, {%1,%2};" : "=l"(u) : "f"(lo), "f"(hi));
    return u;
}
__device__ __forceinline__ float ull_hsum(unsigned long long u) {
    float lo, hi;
    asm("mov.b64 {%0,%1}, %2;" : "=f"(lo), "=f"(hi) : "l"(u));
    return lo + hi;
}
__device__ __forceinline__ float fsigmoid(float x) {
    return __fdividef(1.f, 1.f + __expf(-x));
}
__device__ __forceinline__ float ftanh(float x) {
    float e = __expf(2.f * x);
    return 1.f - __fdividef(2.f, e + 1.f);
}

// ---------------------------------------------------------------------------
// Kernel 1: xw[row,:] = x[row,:] @ Wx + b_in.  (unchanged: ~50/50 L1/FMA,
// 2 CTAs/SM; will get the warp-split treatment in a later round)
// ---------------------------------------------------------------------------
__global__ void __launch_bounds__(384, 2) xw_kernel(const float* __restrict__ inputs,
                                                    const float* __restrict__ Wx,
                                                    const float* __restrict__ bias) {
    __shared__ __align__(16) float xs[64][FDIM];   // 16 KB
    const int row0 = blockIdx.x * 64;
    const int j    = threadIdx.x;

    for (int i = j; i < 64 * FDIM; i += 384) {
        int r = i >> 6, k = i & 63;
        xs[r][k] = inputs[(size_t)(row0 + r) * 65 + k];
    }
    const float bi = bias[j];
    __syncthreads();

    #pragma unroll 1
    for (int rt = 0; rt < 8; rt++) {
        unsigned long long acc[8];
        #pragma unroll
        for (int r = 0; r < 8; r++) acc[r] = 0ull;

        #pragma unroll
        for (int k4 = 0; k4 < FDIM / 4; k4++) {
            float w0 = __ldg(&Wx[(k4 * 4 + 0) * G3 + j]);
            float w1 = __ldg(&Wx[(k4 * 4 + 1) * G3 + j]);
            float w2 = __ldg(&Wx[(k4 * 4 + 2) * G3 + j]);
            float w3 = __ldg(&Wx[(k4 * 4 + 3) * G3 + j]);
            unsigned long long wA = packf2(w0, w1);
            unsigned long long wB = packf2(w2, w3);
            #pragma unroll
            for (int r = 0; r < 8; r++) {
                ulonglong2 x = *reinterpret_cast<const ulonglong2*>(
                    &xs[rt * 8 + r][k4 * 4]);
                ffma2(acc[r], wA, x.x);
                ffma2(acc[r], wB, x.y);
            }
        }
        #pragma unroll
        for (int r = 0; r < 8; r++)
            g_xw[(size_t)(row0 + rt * 8 + r) * G3 + j] = ull_hsum(acc[r]) + bi;
    }
}

// ---------------------------------------------------------------------------
// Kernel 2: GRU scan + fused head. 128 blocks x 384 threads, 4 batches/block.
// WARP-LEVEL split-K: warp w covers k-half (w&1) -> its hs loads stay
// UNIFORM-broadcast (1 wavefront each); lane owns 2 ADJACENT columns
// (col0 = (w>>1)*64 + 2*lane, col1 = col0+1), so each warp touches only
// 256 h-floats/step -> crossbar wavefronts HALVED vs rounds 4-6.
// Weights: 2 cols x 64 k = 128 floats = 64 packed ull in registers.
// Partials combined through smem gpart[2][4][384] in the activation phase.
// ---------------------------------------------------------------------------
__global__ void __launch_bounds__(384, 1) gru_scan_kernel(
        const float* __restrict__ inputs,
        const float* __restrict__ Wh,
        const float* __restrict__ bias,
        const float* __restrict__ W_state,
        const float* __restrict__ w1,
        const float* __restrict__ b1,
        const float* __restrict__ gamma,
        const float* __restrict__ beta,
        const float* __restrict__ mean,
        const float* __restrict__ var,
        const float* __restrict__ w2,
        const float* __restrict__ b2,
        float* __restrict__ out) {
    __shared__ __align__(16) float hs[4][H_DIM];    // current h, 2 KB
    __shared__ float gpart[2][4][G3];               // recurrent partials, 12 KB
    __shared__ float red[4][64];                    // head partials

    const int t    = threadIdx.x;
    const int w    = t >> 5;
    const int lam  = t & 31;
    const int hb   = w & 1;                 // k-half of this warp
    const int kb   = hb * 64;
    const int col0 = (w >> 1) * 64 + lam * 2;   // col1 = col0 + 1
    const int b0   = blockIdx.x * 4;

    // activation-role indices (item1 for all threads, item2 for t<128)
    const int j1 = t & 127;
    const int ab = t >> 7;                  // activation batch, 0..2
    const float brz = bias[G3 + j1];
    const float brr = bias[G3 + 128 + j1];
    const float brh = bias[G3 + 256 + j1];

    // weights -> 64 packed ull (2 cols x 32 k-pairs)
    unsigned long long wc0[32], wc1[32];
    #pragma unroll
    for (int i = 0; i < 32; i++) {
        wc0[i] = packf2(__ldg(&Wh[(kb + 2 * i) * G3 + col0]),
                        __ldg(&Wh[(kb + 2 * i + 1) * G3 + col0]));
        wc1[i] = packf2(__ldg(&Wh[(kb + 2 * i) * G3 + col0 + 1]),
                        __ldg(&Wh[(kb + 2 * i + 1) * G3 + col0 + 1]));
    }

    for (int i = t; i < 4 * H_DIM; i += 384) (&hs[0][0])[i] = 0.f;
    const float* __restrict__ xw1 = g_xw + (size_t)(b0 + ab) * BSTRIDE + j1;
    const float* __restrict__ xw2 = g_xw + (size_t)(b0 + 3) * BSTRIDE + j1;  // t<128
    __syncthreads();

    for (int step = 0; step < T_DIM; step++) {
        const size_t so = (size_t)step * G3;
        // prefetch this step's input preacts for the activation phase
        float x1z = xw1[so], x1r = xw1[so + 128], x1h = xw1[so + 256];
        float x2z = 0.f, x2r = 0.f, x2h = 0.f;
        if (t < 128) { x2z = xw2[so]; x2r = xw2[so + 128]; x2h = xw2[so + 256]; }

        // GEMV over this warp's k-half for 2 columns x 4 batches
        unsigned long long a00 = 0ull, a01 = 0ull, a10 = 0ull, a11 = 0ull;
        unsigned long long a20 = 0ull, a21 = 0ull, a30 = 0ull, a31 = 0ull;
        #pragma unroll
        for (int k4 = 0; k4 < 16; k4++) {
            const int k = kb + 4 * k4;
            ulonglong2 h0 = *reinterpret_cast<const ulonglong2*>(&hs[0][k]);
            ffma2(a00, wc0[2 * k4], h0.x); ffma2(a00, wc0[2 * k4 + 1], h0.y);
            ffma2(a01, wc1[2 * k4], h0.x); ffma2(a01, wc1[2 * k4 + 1], h0.y);
            ulonglong2 h1 = *reinterpret_cast<const ulonglong2*>(&hs[1][k]);
            ffma2(a10, wc0[2 * k4], h1.x); ffma2(a10, wc0[2 * k4 + 1], h1.y);
            ffma2(a11, wc1[2 * k4], h1.x); ffma2(a11, wc1[2 * k4 + 1], h1.y);
            ulonglong2 h2 = *reinterpret_cast<const ulonglong2*>(&hs[2][k]);
            ffma2(a20, wc0[2 * k4], h2.x); ffma2(a20, wc0[2 * k4 + 1], h2.y);
            ffma2(a21, wc1[2 * k4], h2.x); ffma2(a21, wc1[2 * k4 + 1], h2.y);
            ulonglong2 h3 = *reinterpret_cast<const ulonglong2*>(&hs[3][k]);
            ffma2(a30, wc0[2 * k4], h3.x); ffma2(a30, wc0[2 * k4 + 1], h3.y);
            ffma2(a31, wc1[2 * k4], h3.x); ffma2(a31, wc1[2 * k4 + 1], h3.y);
        }
        {
            float2 s;
            s.x = ull_hsum(a00); s.y = ull_hsum(a01);
            *reinterpret_cast<float2*>(&gpart[hb][0][col0]) = s;
            s.x = ull_hsum(a10); s.y = ull_hsum(a11);
            *reinterpret_cast<float2*>(&gpart[hb][1][col0]) = s;
            s.x = ull_hsum(a20); s.y = ull_hsum(a21);
            *reinterpret_cast<float2*>(&gpart[hb][2][col0]) = s;
            s.x = ull_hsum(a30); s.y = ull_hsum(a31);
            *reinterpret_cast<float2*>(&gpart[hb][3][col0]) = s;
        }
        __syncthreads();

        // activation: item1 (all threads), item2 (t < 128, batch 3)
        {
            float z = fsigmoid(x1z + gpart[0][ab][j1] + gpart[1][ab][j1] + brz);
            float r = fsigmoid(x1r + gpart[0][ab][128 + j1] + gpart[1][ab][128 + j1] + brr);
            float hh = ftanh(x1h + r * (gpart[0][ab][256 + j1] + gpart[1][ab][256 + j1] + brh));
            hs[ab][j1] = z * hs[ab][j1] + (1.f - z) * hh;
        }
        if (t < 128) {
            float z = fsigmoid(x2z + gpart[0][3][j1] + gpart[1][3][j1] + brz);
            float r = fsigmoid(x2r + gpart[0][3][128 + j1] + gpart[1][3][128 + j1] + brr);
            float hh = ftanh(x2h + r * (gpart[0][3][256 + j1] + gpart[1][3][256 + j1] + brh));
            hs[3][j1] = z * hs[3][j1] + (1.f - z) * hh;
        }
        __syncthreads();
    }

    // ---- fused head: hidden += W_state[idx]; out = BN(relu(hid@w1+b1)) @ w2 + b2
    for (int i = t; i < 4 * H_DIM; i += 384) {
        int bb = i >> 7, j = i & 127;
        float st = inputs[((size_t)(b0 + bb) * T_DIM + (T_DIM - 1)) * 65 + 64];
        int idx = (int)st;
        idx = idx < 0 ? 0 : (idx > 2 ? 2 : idx);
        gpart[0][bb][j] = hs[bb][j] + W_state[idx * H_DIM + j];
    }
    __syncthreads();

    if (t < 256) {
        int bb = t >> 6, tt = t & 63;
        float a = b1[tt];
        #pragma unroll 8
        for (int k = 0; k < H_DIM; k++)
            a = fmaf(gpart[0][bb][k], w1[k * 64 + tt], a);
        a = fmaxf(a, 0.f);
        a = (a - mean[tt]) * rsqrtf(var[tt] + 1e-3f) * gamma[tt] + beta[tt];
        red[bb][tt] = a * w2[tt];
    }
    __syncthreads();

    if (t < 4) {
        float s = b2[0];
        #pragma unroll 8
        for (int k = 0; k < 64; k++) s += red[t][k];
        out[b0 + t] = s;
    }
}

// ---------------------------------------------------------------------------
extern "C" void kernel_launch(void* const* d_in, const int* in_sizes, int n_in,
                              void* d_out, int out_size) {
    const float* inputs  = (const float*)d_in[0];
    const float* Wx      = (const float*)d_in[1];
    const float* Wh      = (const float*)d_in[2];
    const float* bias    = (const float*)d_in[3];
    const float* W_state = (const float*)d_in[4];
    const float* w1      = (const float*)d_in[5];
    const float* b1      = (const float*)d_in[6];
    const float* gamma   = (const float*)d_in[7];
    const float* beta    = (const float*)d_in[8];
    const float* mean    = (const float*)d_in[9];
    const float* var     = (const float*)d_in[10];
    const float* w2      = (const float*)d_in[11];
    const float* b2      = (const float*)d_in[12];
    float* out = (float*)d_out;

    xw_kernel<<<(B_DIM * T_DIM) / 64, 384>>>(inputs, Wx, bias);
    gru_scan_kernel<<<B_DIM / 4, 384>>>(inputs, Wh, bias, W_state, w1, b1,
                                        gamma, beta, mean, var, w2, b2, out);
}